// round 3
// baseline (speedup 1.0000x reference)
#include <cuda_runtime.h>
#include <math.h>

// ---------------------------------------------------------------------------
// Scratch (allocation-free rule: __device__ globals)
// ---------------------------------------------------------------------------
__device__ float g_x [4194304];    // running residual [4096,1024]
__device__ float g_h [4194304];    // layernorm output
__device__ float g_q [4194304];
__device__ float g_k [4194304];
__device__ float g_v [4194304];
__device__ float g_o [4194304];    // attention output (pre out-proj)
__device__ float g_S [134217728];  // scores [2,16,2048,2048] (reused for cross w/ ld=80)
__device__ float g_hg[33554432];   // FFN intermediate [4096,8192]
__device__ float g_gg[16777216];   // GEGLU output [4096,4096]

// ---------------------------------------------------------------------------
// LayerNorm: one CTA (128 threads) per row of 1024
// ---------------------------------------------------------------------------
__global__ void ln_kernel(const float* __restrict__ x, const float* __restrict__ gamma,
                          const float* __restrict__ beta, float* __restrict__ out)
{
    __shared__ float red[4];
    const long long row = blockIdx.x;
    const float* xr = x + row * 1024;
    const int t = threadIdx.x;
    float v[8];
    *reinterpret_cast<float4*>(&v[0]) = *reinterpret_cast<const float4*>(xr + t * 8);
    *reinterpret_cast<float4*>(&v[4]) = *reinterpret_cast<const float4*>(xr + t * 8 + 4);
    float s = 0.f;
#pragma unroll
    for (int i = 0; i < 8; ++i) s += v[i];
#pragma unroll
    for (int o = 16; o; o >>= 1) s += __shfl_xor_sync(0xffffffffu, s, o);
    if ((t & 31) == 0) red[t >> 5] = s;
    __syncthreads();
    const float mu = (red[0] + red[1] + red[2] + red[3]) * (1.0f / 1024.0f);
    __syncthreads();
    float ss = 0.f;
#pragma unroll
    for (int i = 0; i < 8; ++i) { float d = v[i] - mu; ss += d * d; }
#pragma unroll
    for (int o = 16; o; o >>= 1) ss += __shfl_xor_sync(0xffffffffu, ss, o);
    if ((t & 31) == 0) red[t >> 5] = ss;
    __syncthreads();
    const float var = (red[0] + red[1] + red[2] + red[3]) * (1.0f / 1024.0f);
    const float rs = rsqrtf(var + 1e-5f);
    float* orow = out + row * 1024;
#pragma unroll
    for (int i = 0; i < 8; ++i) {
        const int c = t * 8 + i;
        orow[c] = (v[i] - mu) * rs * gamma[c] + beta[c];
    }
}

// ---------------------------------------------------------------------------
// Softmax + 8-bit fake quant (zp=0) in place. One CTA (128 thr) per row.
// Pads columns [L, ld) with zeros (so padded K in the following GEMM is inert).
// ---------------------------------------------------------------------------
__global__ void softmax_quant_kernel(float* __restrict__ S, int L, int ld,
                                     const float* __restrict__ dptr)
{
    __shared__ float buf[2048];
    __shared__ float red[4];
    const long long row = blockIdx.x;
    float* r = S + row * (long long)ld;
    const int t = threadIdx.x;
    float mx = -3.0e38f;
    for (int j = t; j < L; j += 128) { float v = r[j]; buf[j] = v; mx = fmaxf(mx, v); }
#pragma unroll
    for (int o = 16; o; o >>= 1) mx = fmaxf(mx, __shfl_xor_sync(0xffffffffu, mx, o));
    if ((t & 31) == 0) red[t >> 5] = mx;
    __syncthreads();
    mx = fmaxf(fmaxf(red[0], red[1]), fmaxf(red[2], red[3]));
    __syncthreads();
    float s = 0.f;
    for (int j = t; j < L; j += 128) s += expf(buf[j] - mx);
#pragma unroll
    for (int o = 16; o; o >>= 1) s += __shfl_xor_sync(0xffffffffu, s, o);
    if ((t & 31) == 0) red[t >> 5] = s;
    __syncthreads();
    s = red[0] + red[1] + red[2] + red[3];
    const float delta = *dptr;
    for (int j = t; j < L; j += 128) {
        const float p  = expf(buf[j] - mx) / s;
        float xi = rintf(p / delta);                 // zp = 0
        xi = fminf(fmaxf(xi, 0.f), 255.f);
        r[j] = xi * delta;
    }
    for (int j = L + t; j < ld; j += 128) r[j] = 0.f;
}

// ---------------------------------------------------------------------------
// GEGLU: gg[r][c] = hg[r][c] * gelu_exact(hg[r][4096+c])   (4096x4096, float4)
// ---------------------------------------------------------------------------
__global__ void geglu_kernel(const float* __restrict__ hg, float* __restrict__ gg)
{
    const long long i4 = (long long)blockIdx.x * blockDim.x + threadIdx.x;
    const long long r  = i4 >> 10;              // 1024 float4 per 4096-wide row
    const long long c  = (i4 & 1023) << 2;
    const float4 a = *reinterpret_cast<const float4*>(hg + r * 8192 + c);
    const float4 g = *reinterpret_cast<const float4*>(hg + r * 8192 + 4096 + c);
    const float k = 0.70710678118654752440f;
    float4 o;
    o.x = a.x * (0.5f * g.x * (1.f + erff(g.x * k)));
    o.y = a.y * (0.5f * g.y * (1.f + erff(g.y * k)));
    o.z = a.z * (0.5f * g.z * (1.f + erff(g.z * k)));
    o.w = a.w * (0.5f * g.w * (1.f + erff(g.w * k)));
    *reinterpret_cast<float4*>(gg + r * 4096 + c) = o;
}

// ---------------------------------------------------------------------------
// Generic tiled SGEMM.
//   C = scale * (A @ op(B)) [+ bias[n]] [+ res] [-> fake-quant(delta, zp)]
//   A: [M,K] row-major (lda).   BT=false: B is [K,N] (ldb).  BT=true: B is [N,K] (ldb).
//   Batched over blockIdx.z = b*16 + h with independent (b,h) strides.
//   BK = 16; K must be a multiple of 16 and 16B-aligned rows (guaranteed by caller).
// ---------------------------------------------------------------------------
template<int BM, int BN, int TM, int TN, bool BT>
__global__ void __launch_bounds__(256, 2)
gemm_kernel(const float* __restrict__ A, const float* __restrict__ Bm, float* __restrict__ C,
            int M, int N, int K, int lda, int ldb, int ldc,
            long long sAb, long long sAh, long long sBb, long long sBh,
            long long sCb, long long sCh,
            const float* __restrict__ bias,
            const float* __restrict__ res, long long sRb, long long sRh, int ldr,
            const float* __restrict__ dptr, float zp, float scale)
{
    __shared__ float As[16][BM + 4];
    __shared__ float Bs[16][BN + 4];

    const int bz = blockIdx.z;
    const int hb = bz & 15;
    const int bb = bz >> 4;
    A  += bb * sAb + hb * sAh;
    Bm += bb * sBb + hb * sBh;
    C  += bb * sCb + hb * sCh;
    if (res) res += bb * sRb + hb * sRh;

    const int bm = blockIdx.y * BM;
    const int bn = blockIdx.x * BN;
    const int tid = threadIdx.x;
    constexpr int TCOLS = BN / TN;
    const int tcol = tid % TCOLS;
    const int trow = tid / TCOLS;

    float acc[TM][TN];
#pragma unroll
    for (int i = 0; i < TM; ++i)
#pragma unroll
        for (int j = 0; j < TN; ++j) acc[i][j] = 0.f;

    constexpr int A_ITERS = (BM * 16) / 1024;
    constexpr int B_ITERS = (BN * 16) / 1024;

    for (int k0 = 0; k0 < K; k0 += 16) {
        // ---- load A tile [BM x 16], transposed into As[k][m] ----
#pragma unroll
        for (int i = 0; i < A_ITERS; ++i) {
            const int idx = tid + i * 256;
            const int r  = idx >> 2;     // 4 float4 per row (BK=16)
            const int c4 = idx & 3;
            const int gr = bm + r;
            float4 a = make_float4(0.f, 0.f, 0.f, 0.f);
            if (gr < M)
                a = *reinterpret_cast<const float4*>(A + (long long)gr * lda + k0 + c4 * 4);
            As[c4 * 4 + 0][r] = a.x;
            As[c4 * 4 + 1][r] = a.y;
            As[c4 * 4 + 2][r] = a.z;
            As[c4 * 4 + 3][r] = a.w;
        }
        // ---- load B tile into Bs[k][n] ----
        if (BT) {
#pragma unroll
            for (int i = 0; i < B_ITERS; ++i) {
                const int idx = tid + i * 256;
                const int r  = idx >> 2;
                const int c4 = idx & 3;
                const int gn = bn + r;
                float4 b = make_float4(0.f, 0.f, 0.f, 0.f);
                if (gn < N)
                    b = *reinterpret_cast<const float4*>(Bm + (long long)gn * ldb + k0 + c4 * 4);
                Bs[c4 * 4 + 0][r] = b.x;
                Bs[c4 * 4 + 1][r] = b.y;
                Bs[c4 * 4 + 2][r] = b.z;
                Bs[c4 * 4 + 3][r] = b.w;
            }
        } else {
            constexpr int C4R = BN / 4;
#pragma unroll
            for (int i = 0; i < B_ITERS; ++i) {
                const int idx = tid + i * 256;
                const int r  = idx / C4R;
                const int c4 = idx % C4R;
                const int gk = k0 + r;
                const int gn = bn + c4 * 4;
                float4 b = make_float4(0.f, 0.f, 0.f, 0.f);
                if (gk < K) {
                    if (gn + 3 < N) {
                        b = *reinterpret_cast<const float4*>(Bm + (long long)gk * ldb + gn);
                    } else {
                        const float* bp = Bm + (long long)gk * ldb + gn;
                        b.x = (gn + 0 < N) ? bp[0] : 0.f;
                        b.y = (gn + 1 < N) ? bp[1] : 0.f;
                        b.z = (gn + 2 < N) ? bp[2] : 0.f;
                        b.w = (gn + 3 < N) ? bp[3] : 0.f;
                    }
                }
                *reinterpret_cast<float4*>(&Bs[r][c4 * 4]) = b;
            }
        }
        __syncthreads();

#pragma unroll
        for (int kk = 0; kk < 16; ++kk) {
            float af[TM], bf[TN];
#pragma unroll
            for (int i = 0; i < TM; i += 4)
                *reinterpret_cast<float4*>(&af[i]) =
                    *reinterpret_cast<const float4*>(&As[kk][trow * TM + i]);
#pragma unroll
            for (int j = 0; j < TN; j += 4)
                *reinterpret_cast<float4*>(&bf[j]) =
                    *reinterpret_cast<const float4*>(&Bs[kk][tcol * TN + j]);
#pragma unroll
            for (int i = 0; i < TM; ++i)
#pragma unroll
                for (int j = 0; j < TN; ++j)
                    acc[i][j] = fmaf(af[i], bf[j], acc[i][j]);
        }
        __syncthreads();
    }

    // ---- epilogue ----
    float delta = 1.f;
    if (dptr) delta = *dptr;
#pragma unroll
    for (int i = 0; i < TM; ++i) {
        const int r = bm + trow * TM + i;
        if (r >= M) continue;
#pragma unroll
        for (int j = 0; j < TN; ++j) {
            const int c = bn + tcol * TN + j;
            if (c >= N) continue;
            float v = acc[i][j] * scale;
            if (bias) v += bias[c];
            if (res)  v += res[(long long)r * ldr + c];
            if (dptr) {
                float xi = rintf(v / delta) + zp;
                xi = fminf(fmaxf(xi, 0.f), 255.f);
                v = (xi - zp) * delta;
            }
            C[(long long)r * ldc + c] = v;
        }
    }
}

template<int BM, int BN, int TM, int TN, bool BT>
static void run_gemm(const float* A, const float* B, float* C,
                     int M, int N, int K, int lda, int ldb, int ldc,
                     long long sAb, long long sAh, long long sBb, long long sBh,
                     long long sCb, long long sCh, int nbatch,
                     const float* bias,
                     const float* res, long long sRb, long long sRh, int ldr,
                     const float* dptr, float zp, float scale)
{
    dim3 grid((N + BN - 1) / BN, (M + BM - 1) / BM, nbatch);
    gemm_kernel<BM, BN, TM, TN, BT><<<grid, 256>>>(
        A, B, C, M, N, K, lda, ldb, ldc,
        sAb, sAh, sBb, sBh, sCb, sCh,
        bias, res, sRb, sRh, ldr, dptr, zp, scale);
}

// ---------------------------------------------------------------------------
// kernel_launch
// ---------------------------------------------------------------------------
extern "C" void kernel_launch(void* const* d_in, const int* in_sizes, int n_in,
                              void* d_out, int out_size)
{
    (void)in_sizes; (void)n_in; (void)out_size;
    const float* x     = (const float*)d_in[0];
    const float* ctx   = (const float*)d_in[1];
    const float* ln1_g = (const float*)d_in[2];
    const float* ln1_b = (const float*)d_in[3];
    const float* ln2_g = (const float*)d_in[4];
    const float* ln2_b = (const float*)d_in[5];
    const float* ln3_g = (const float*)d_in[6];
    const float* ln3_b = (const float*)d_in[7];
    const float* wq1 = (const float*)d_in[8];
    const float* wk1 = (const float*)d_in[9];
    const float* wv1 = (const float*)d_in[10];
    const float* wo1 = (const float*)d_in[11];
    const float* bo1 = (const float*)d_in[12];
    const float* wq2 = (const float*)d_in[13];
    const float* wk2 = (const float*)d_in[14];
    const float* wv2 = (const float*)d_in[15];
    const float* wo2 = (const float*)d_in[16];
    const float* bo2 = (const float*)d_in[17];
    const float* w1  = (const float*)d_in[18];
    const float* b1  = (const float*)d_in[19];
    const float* w2  = (const float*)d_in[20];
    const float* b2  = (const float*)d_in[21];
    const float* dq1 = (const float*)d_in[22];
    const float* dk1 = (const float*)d_in[23];
    const float* dv1 = (const float*)d_in[24];
    const float* dw1 = (const float*)d_in[25];
    const float* dq2 = (const float*)d_in[26];
    const float* dk2 = (const float*)d_in[27];
    const float* dv2 = (const float*)d_in[28];
    const float* dw2 = (const float*)d_in[29];
    float* out = (float*)d_out;

    float *px, *ph, *pq, *pk, *pv, *po, *pS, *phg, *pgg;
    cudaGetSymbolAddress((void**)&px,  g_x);
    cudaGetSymbolAddress((void**)&ph,  g_h);
    cudaGetSymbolAddress((void**)&pq,  g_q);
    cudaGetSymbolAddress((void**)&pk,  g_k);
    cudaGetSymbolAddress((void**)&pv,  g_v);
    cudaGetSymbolAddress((void**)&po,  g_o);
    cudaGetSymbolAddress((void**)&pS,  g_S);
    cudaGetSymbolAddress((void**)&phg, g_hg);
    cudaGetSymbolAddress((void**)&pgg, g_gg);

    const long long ND  = 2048LL * 1024;       // per-b stride of q/k/v/o/x (b-major)
    const long long SB1 = 16LL * 2048 * 2048;  // S1 per-b stride
    const long long SH1 = 2048LL * 2048;       // S1 per-h stride
    const long long SB2 = 16LL * 2048 * 80;    // S2 per-b stride (padded ld=80)
    const long long SH2 = 2048LL * 80;
    const long long CKV = 77LL * 1024;         // cross K/V per-b stride

    // ================= self attention =================
    ln_kernel<<<4096, 128>>>(x, ln1_g, ln1_b, ph);
    run_gemm<128,128,8,8,false>(ph, wq1, pq, 4096,1024,1024, 1024,1024,1024,
        0,0, 0,0, 0,0, 1, nullptr, nullptr,0,0,0, dq1, 128.f, 1.f);
    run_gemm<128,128,8,8,false>(ph, wk1, pk, 4096,1024,1024, 1024,1024,1024,
        0,0, 0,0, 0,0, 1, nullptr, nullptr,0,0,0, dk1, 128.f, 1.f);
    run_gemm<128,128,8,8,false>(ph, wv1, pv, 4096,1024,1024, 1024,1024,1024,
        0,0, 0,0, 0,0, 1, nullptr, nullptr,0,0,0, dv1, 128.f, 1.f);
    // S1[b,h] = fq(q) @ fq(k)^T * 0.125
    run_gemm<128,128,8,8,true>(pq, pk, pS, 2048,2048,64, 1024,1024,2048,
        ND,64, ND,64, SB1,SH1, 32, nullptr, nullptr,0,0,0, nullptr, 0.f, 0.125f);
    softmax_quant_kernel<<<65536, 128>>>(pS, 2048, 2048, dw1);
    // O1[b,h] = P @ fq(v)
    run_gemm<128,64,8,4,false>(pS, pv, po, 2048,64,2048, 2048,1024,1024,
        SB1,SH1, ND,64, ND,64, 32, nullptr, nullptr,0,0,0, nullptr, 0.f, 1.f);
    // x = O1 @ wo1 + bo1 + x
    run_gemm<128,128,8,8,false>(po, wo1, px, 4096,1024,1024, 1024,1024,1024,
        0,0, 0,0, 0,0, 1, bo1, x, 0,0,1024, nullptr, 0.f, 1.f);

    // ================= cross attention =================
    ln_kernel<<<4096, 128>>>(px, ln2_g, ln2_b, ph);
    run_gemm<128,128,8,8,false>(ph, wq2, pq, 4096,1024,1024, 1024,1024,1024,
        0,0, 0,0, 0,0, 1, nullptr, nullptr,0,0,0, dq2, 128.f, 1.f);
    run_gemm<128,128,8,8,false>(ctx, wk2, pk, 154,1024,1024, 1024,1024,1024,
        0,0, 0,0, 0,0, 1, nullptr, nullptr,0,0,0, dk2, 128.f, 1.f);
    run_gemm<128,128,8,8,false>(ctx, wv2, pv, 154,1024,1024, 1024,1024,1024,
        0,0, 0,0, 0,0, 1, nullptr, nullptr,0,0,0, dv2, 128.f, 1.f);
    // S2[b,h] = fq(q) @ fq(k)^T * 0.125   (N=77, stored ld=80)
    run_gemm<128,128,8,8,true>(pq, pk, pS, 2048,77,64, 1024,1024,80,
        ND,64, CKV,64, SB2,SH2, 32, nullptr, nullptr,0,0,0, nullptr, 0.f, 0.125f);
    softmax_quant_kernel<<<65536, 128>>>(pS, 77, 80, dw2);   // zero-pads cols 77..79
    // O2[b,h] = P @ fq(v)   (K padded to 80; pad cols are exact zeros)
    run_gemm<128,64,8,4,false>(pS, pv, po, 2048,64,80, 80,1024,1024,
        SB2,SH2, CKV,64, ND,64, 32, nullptr, nullptr,0,0,0, nullptr, 0.f, 1.f);
    // x = O2 @ wo2 + bo2 + x   (in-place residual: each element read+written by its own thread)
    run_gemm<128,128,8,8,false>(po, wo2, px, 4096,1024,1024, 1024,1024,1024,
        0,0, 0,0, 0,0, 1, bo2, px, 0,0,1024, nullptr, 0.f, 1.f);

    // ================= GEGLU feed-forward =================
    ln_kernel<<<4096, 128>>>(px, ln3_g, ln3_b, ph);
    run_gemm<128,128,8,8,false>(ph, w1, phg, 4096,8192,1024, 1024,8192,8192,
        0,0, 0,0, 0,0, 1, b1, nullptr,0,0,0, nullptr, 0.f, 1.f);
    geglu_kernel<<<16384, 256>>>(phg, pgg);
    run_gemm<128,128,8,8,false>(pgg, w2, out, 4096,1024,4096, 4096,1024,1024,
        0,0, 0,0, 0,0, 1, b2, px, 0,0,1024, nullptr, 0.f, 1.f);
}